// round 12
// baseline (speedup 1.0000x reference)
#include <cuda_runtime.h>
#include <cuda_fp16.h>
#include <cstdint>

#define B_     32
#define NPOS   25088
#define NCHUNK 1312     // 32 icb * 41 k16-chunks (koff padded 81->82)

// staged x: [b][icb][ih64][q32][parity2][p4][hi4B|lo4B] fp16 -> 131072 B per (b,icb)
__device__ __align__(16) unsigned char g_x[32u * 32u * 131072u];
// packed B fragments: [chunk][g4][col8][p4][hi8B|lo8B] -> 2048 B per chunk
__device__ __align__(16) unsigned char g_wb[(size_t)NCHUNK * 2048u];

// ---------------- x prep: f32 -> fp16 hi/lo, fully contiguous 64B stores ----------------
__global__ void xprep(const float* __restrict__ x) {
    int i = blockIdx.x * 256 + threadIdx.x;          // 2097152 total
    int q = i & 31, r = (i >> 5) & 63, icb = (i >> 11) & 31, b = i >> 16;
    const float* xp = x + (((size_t)b * 256 + icb * 8) * 64 + r) * 64 + 2 * q;
    uint32_t h0[4], h1[4], l0[4], l1[4];             // parity0 (iw=2q), parity1 (iw=2q+1)
    #pragma unroll
    for (int j = 0; j < 4; ++j) {                    // j = ic pair p
        uint32_t ha = 0, hb = 0, la = 0, lb = 0;
        #pragma unroll
        for (int e = 0; e < 2; ++e) {                // e = ic within pair
            float2 v = *reinterpret_cast<const float2*>(xp + (size_t)(2 * j + e) * 4096);
            __half hx = __float2half_rn(v.x);
            __half hy = __float2half_rn(v.y);
            __half lx = __float2half_rn(v.x - __half2float(hx));
            __half ly = __float2half_rn(v.y - __half2float(hy));
            ha |= (uint32_t)__half_as_ushort(hx) << (e * 16);
            hb |= (uint32_t)__half_as_ushort(hy) << (e * 16);
            la |= (uint32_t)__half_as_ushort(lx) << (e * 16);
            lb |= (uint32_t)__half_as_ushort(ly) << (e * 16);
        }
        h0[j] = ha; h1[j] = hb; l0[j] = la; l1[j] = lb;
    }
    // layout: ih*2048 + q*64 + parity*32 + p*8 ; thread writes 64B contiguous
    size_t ub = (size_t)(b * 32 + icb) * 131072u + (uint32_t)r * 2048u + (uint32_t)q * 64u;
    *reinterpret_cast<uint4*>(g_x + ub)      = make_uint4(h0[0], l0[0], h0[1], l0[1]);
    *reinterpret_cast<uint4*>(g_x + ub + 16) = make_uint4(h0[2], l0[2], h0[3], l0[3]);
    *reinterpret_cast<uint4*>(g_x + ub + 32) = make_uint4(h1[0], l1[0], h1[1], l1[1]);
    *reinterpret_cast<uint4*>(g_x + ub + 48) = make_uint4(h1[2], l1[2], h1[3], l1[3]);
}

// ---------------- W prep: B fragments, hi/lo interleaved per lane (16B) ----------------
__global__ void wprep(const float* __restrict__ W) {
    int i = blockIdx.x * 256 + threadIdx.x;          // NCHUNK*128 = 167936
    if (i >= NCHUNK * 128) return;
    int p = i & 3, oc = (i >> 2) & 31, c = i >> 7;
    int icb = c / 41, j = c - icb * 41;
    int k0 = 2 * j, k1 = k0 + 1;                     // k1 == 81 -> zero pad
    unsigned short hh[4], ll[4];
    #pragma unroll
    for (int kk = 0; kk < 2; ++kk) {
        int koff = kk ? k1 : k0;
        #pragma unroll
        for (int e = 0; e < 2; ++e) {
            int ic = icb * 8 + 2 * p + e;
            float v = (koff <= 80) ? W[((size_t)oc * 256 + ic) * 81 + koff] : 0.f;
            __half h = __float2half_rn(v);
            __half l = __float2half_rn(v - __half2float(h));
            hh[kk * 2 + e] = __half_as_ushort(h);
            ll[kk * 2 + e] = __half_as_ushort(l);
        }
    }
    uint4 pk = make_uint4((uint32_t)hh[0] | ((uint32_t)hh[1] << 16),
                          (uint32_t)hh[2] | ((uint32_t)hh[3] << 16),
                          (uint32_t)ll[0] | ((uint32_t)ll[1] << 16),
                          (uint32_t)ll[2] | ((uint32_t)ll[3] << 16));
    size_t off = (size_t)c * 2048 + (oc >> 3) * 512 + (oc & 7) * 64 + p * 16;
    *reinterpret_cast<uint4*>(g_wb + off) = pk;
}

// ---------------- main: fp16 mma implicit GEMM, depth-2 pipeline ----------------
__device__ __forceinline__ void mma_f32(float* c, const uint32_t* a, uint32_t b0, uint32_t b1) {
    asm volatile("mma.sync.aligned.m16n8k16.row.col.f32.f16.f16.f32 "
        "{%0,%1,%2,%3}, {%4,%5,%6,%7}, {%8,%9}, {%0,%1,%2,%3};"
        : "+f"(c[0]), "+f"(c[1]), "+f"(c[2]), "+f"(c[3])
        : "r"(a[0]), "r"(a[1]), "r"(a[2]), "r"(a[3]), "r"(b0), "r"(b1));
}
__device__ __forceinline__ void mma_f16(uint32_t* c, const uint32_t* a, uint32_t b0, uint32_t b1) {
    asm volatile("mma.sync.aligned.m16n8k16.row.col.f16.f16.f16.f16 "
        "{%0,%1}, {%2,%3,%4,%5}, {%6,%7}, {%0,%1};"
        : "+r"(c[0]), "+r"(c[1])
        : "r"(a[0]), "r"(a[1]), "r"(a[2]), "r"(a[3]), "r"(b0), "r"(b1));
}

__global__ __launch_bounds__(128, 3)
void conv_mma(const float* __restrict__ bias, float* __restrict__ out) {
    __shared__ int s_i0[NCHUNK], s_i1[NCHUNK];
    __shared__ float s_bias[32];
    const int tid = threadIdx.x, wid = tid >> 5, lane = tid & 31;

    for (int c = tid; c < NCHUNK; c += 128) {
        int icb = c / 41, j = c - icb * 41;
        int k0 = 2 * j, k1 = (k0 < 80) ? k0 + 1 : 80;   // pad chunk reuses 80's addr (B half = 0)
        int kh0 = k0 / 9, kw0 = k0 - 9 * kh0;
        int kh1 = k1 / 9, kw1 = k1 - 9 * kh1;
        s_i0[c] = icb * 131072 + kh0 * 2048 + (kw0 >> 1) * 64 + (kw0 & 1) * 32;
        s_i1[c] = icb * 131072 + kh1 * 2048 + (kw1 >> 1) * 64 + (kw1 & 1) * 32;
    }
    if (tid < 32) s_bias[tid] = bias[tid];
    __syncthreads();

    // warp-tile: 1568 = 32 b x 49 m16 tiles; pos = tile*16 + row
    const int gidx = blockIdx.x * 4 + wid;
    const int b    = gidx / 49;
    const int tile = gidx - b * 49;
    const int pos_a = tile * 16 + (lane >> 2);
    const int pos_b = pos_a + 8;
    const int oh_a = pos_a / 28, ow_a = pos_a - 28 * oh_a;
    const int oh_b = pos_b / 28, ow_b = pos_b - 28 * oh_b;
    // A addr = s_iX[c] + oh*4096 + ow*64 + p*8   (ih*2048 & iw-parity folded into s_iX)
    const uint32_t oA = (uint32_t)(oh_a * 4096 + ow_a * 64 + (lane & 3) * 8);
    const uint32_t oB = (uint32_t)(oh_b * 4096 + ow_b * 64 + (lane & 3) * 8);
    const unsigned char* xb  = g_x  + (size_t)b * (32u * 131072u);
    const unsigned char* wbp = g_wb + ((lane >> 2) * 64 + (lane & 3) * 16);

    float acc[4][4];
    uint32_t accc[4][2];                  // f16x2 cross accumulators
    #pragma unroll
    for (int g = 0; g < 4; ++g) {
        #pragma unroll
        for (int q = 0; q < 4; ++q) acc[g][q] = 0.f;
        accc[g][0] = 0u; accc[g][1] = 0u;
    }

    // depth-2 pipeline buffers
    uint2 A[2][4];                 // .x = hi, .y = lo
    uint4 Bv[2][4];                // .x,.y = hi frag; .z,.w = lo frag
    #pragma unroll
    for (int s = 0; s < 2; ++s) {
        const int u0 = s_i0[s], u1 = s_i1[s];
        A[s][0] = *(const uint2*)(xb + u0 + oA);
        A[s][1] = *(const uint2*)(xb + u0 + oB);
        A[s][2] = *(const uint2*)(xb + u1 + oA);
        A[s][3] = *(const uint2*)(xb + u1 + oB);
        const unsigned char* wp = wbp + (size_t)s * 2048;
        #pragma unroll
        for (int g = 0; g < 4; ++g) Bv[s][g] = *(const uint4*)(wp + g * 512);
    }

    #pragma unroll 2
    for (int c = 0; c < NCHUNK; ++c) {
        const int cur = c & 1;
        uint32_t Ah[4] = {A[cur][0].x, A[cur][1].x, A[cur][2].x, A[cur][3].x};
        uint32_t Al[4] = {A[cur][0].y, A[cur][1].y, A[cur][2].y, A[cur][3].y};
        #pragma unroll
        for (int g = 0; g < 4; ++g) {
            mma_f32(acc[g],  Ah, Bv[cur][g].x, Bv[cur][g].y);   // xh * wh  (fp32 acc)
            mma_f16(accc[g], Al, Bv[cur][g].x, Bv[cur][g].y);   // xl * wh  (fp16 acc)
            mma_f16(accc[g], Ah, Bv[cur][g].z, Bv[cur][g].w);   // xh * wl  (fp16 acc)
        }
        // prefetch chunk c+2 into the buffer just consumed
        const int cn = (c + 2 < NCHUNK) ? c + 2 : c;
        const int u0 = s_i0[cn], u1 = s_i1[cn];
        A[cur][0] = *(const uint2*)(xb + u0 + oA);
        A[cur][1] = *(const uint2*)(xb + u0 + oB);
        A[cur][2] = *(const uint2*)(xb + u1 + oA);
        A[cur][3] = *(const uint2*)(xb + u1 + oB);
        const unsigned char* wp = wbp + (size_t)cn * 2048;
        #pragma unroll
        for (int g = 0; g < 4; ++g) Bv[cur][g] = *(const uint4*)(wp + g * 512);
    }

    // epilogue: main + cross + bias + squash + T=8 broadcast
    float4* o4 = reinterpret_cast<float4*>(out);
    const size_t ob = (size_t)b * NPOS;
    #pragma unroll
    for (int g = 0; g < 4; ++g) {
        float2 cr0 = __half22float2(*reinterpret_cast<const __half2*>(&accc[g][0]));
        float2 cr1 = __half22float2(*reinterpret_cast<const __half2*>(&accc[g][1]));
        float cross[4] = {cr0.x, cr0.y, cr1.x, cr1.y};
        #pragma unroll
        for (int q = 0; q < 4; ++q) {
            const int pos = (q < 2) ? pos_a : pos_b;
            const int oc  = g * 8 + (lane & 3) * 2 + (q & 1);
            float v = acc[g][q] + cross[q] + s_bias[oc];
            float sq = 8.f * v * v;
            float sv = v * (sq / (1.f + sq)) * rsqrtf(sq + 1e-8f);
            float4 f4 = make_float4(sv, sv, sv, sv);
            size_t idx = (ob + (size_t)(oc * 784 + pos)) * 2;
            o4[idx]     = f4;
            o4[idx + 1] = f4;
        }
    }
}

extern "C" void kernel_launch(void* const* d_in, const int* in_sizes, int n_in,
                              void* d_out, int out_size) {
    const float* x    = (const float*)d_in[0];
    const float* W    = (const float*)d_in[1];
    const float* bias = (const float*)d_in[2];
    float* out = (float*)d_out;

    xprep<<<2097152 / 256, 256>>>(x);
    wprep<<<(NCHUNK * 128 + 255) / 256, 256>>>(W);
    conv_mma<<<392, 128>>>(bias, out);   // 392 CTAs = 1568 warp-tiles / 4
}

// round 13
// speedup vs baseline: 1.2958x; 1.2958x over previous
#include <cuda_runtime.h>
#include <cuda_fp16.h>
#include <cstdint>

#define B_     32
#define NPOS   25088
#define NCHUNK 1312     // 32 icb * 41 k16-chunks (koff padded 81->82)

// staged x: [b][icb][ih64][parity2][q32][p4][hi4B|lo4B] fp16 -> 131072 B per (b,icb)
__device__ __align__(16) unsigned char g_x[32u * 32u * 131072u];
// packed B fragments (hi limb only): [chunk][g4][lane32][8B] -> 1024 B per chunk
__device__ __align__(16) unsigned char g_wb[(size_t)NCHUNK * 1024u];

// ---------------- x prep: f32 -> fp16 hi/lo interleaved, parity-split ----------------
__global__ void xprep(const float* __restrict__ x) {
    int i = blockIdx.x * 256 + threadIdx.x;          // 2097152 total
    int q = i & 31, r = (i >> 5) & 63, icb = (i >> 11) & 31, b = i >> 16;
    const float* xp = x + (((size_t)b * 256 + icb * 8) * 64 + r) * 64 + 2 * q;
    uint32_t h0[4], h1[4], l0[4], l1[4];
    #pragma unroll
    for (int j = 0; j < 4; ++j) {
        uint32_t ha = 0, hb = 0, la = 0, lb = 0;
        #pragma unroll
        for (int e = 0; e < 2; ++e) {
            float2 v = *reinterpret_cast<const float2*>(xp + (size_t)(2 * j + e) * 4096);
            __half hx = __float2half_rn(v.x);
            __half hy = __float2half_rn(v.y);
            __half lx = __float2half_rn(v.x - __half2float(hx));
            __half ly = __float2half_rn(v.y - __half2float(hy));
            ha |= (uint32_t)__half_as_ushort(hx) << (e * 16);
            hb |= (uint32_t)__half_as_ushort(hy) << (e * 16);
            la |= (uint32_t)__half_as_ushort(lx) << (e * 16);
            lb |= (uint32_t)__half_as_ushort(ly) << (e * 16);
        }
        h0[j] = ha; h1[j] = hb; l0[j] = la; l1[j] = lb;
    }
    size_t ub = (size_t)(b * 32 + icb) * 131072u + (uint32_t)r * 2048u + (uint32_t)q * 32u;
    *reinterpret_cast<uint4*>(g_x + ub)          = make_uint4(h0[0], l0[0], h0[1], l0[1]);
    *reinterpret_cast<uint4*>(g_x + ub + 16)     = make_uint4(h0[2], l0[2], h0[3], l0[3]);
    *reinterpret_cast<uint4*>(g_x + ub + 1024)   = make_uint4(h1[0], l1[0], h1[1], l1[1]);
    *reinterpret_cast<uint4*>(g_x + ub + 1040)   = make_uint4(h1[2], l1[2], h1[3], l1[3]);
}

// ---------------- W prep: B fragments, hi limb only (8B per lane) ----------------
__global__ void wprep(const float* __restrict__ W) {
    int i = blockIdx.x * 256 + threadIdx.x;          // NCHUNK*128 = 167936
    if (i >= NCHUNK * 128) return;
    int p = i & 3, oc = (i >> 2) & 31, c = i >> 7;
    int icb = c / 41, j = c - icb * 41;
    int k0 = 2 * j, k1 = k0 + 1;                     // k1 == 81 -> zero pad
    unsigned short hh[4];
    #pragma unroll
    for (int kk = 0; kk < 2; ++kk) {
        int koff = kk ? k1 : k0;
        #pragma unroll
        for (int e = 0; e < 2; ++e) {
            int ic = icb * 8 + 2 * p + e;
            float v = (koff <= 80) ? W[((size_t)oc * 256 + ic) * 81 + koff] : 0.f;
            hh[kk * 2 + e] = __half_as_ushort(__float2half_rn(v));
        }
    }
    uint2 pk = make_uint2((uint32_t)hh[0] | ((uint32_t)hh[1] << 16),
                          (uint32_t)hh[2] | ((uint32_t)hh[3] << 16));
    // layout: [chunk][g4][col8][p4] -> g = oc>>3 at stride 256, col = oc&7 at 32, p at 8
    size_t off = (size_t)c * 1024 + (oc >> 3) * 256 + (oc & 7) * 32 + p * 8;
    *reinterpret_cast<uint2*>(g_wb + off) = pk;
}

// ---------------- main: 2-product fp16 mma implicit GEMM + fused squash ----------------
__device__ __forceinline__ void mma_f32(float* c, const uint32_t* a, uint32_t b0, uint32_t b1) {
    asm volatile("mma.sync.aligned.m16n8k16.row.col.f32.f16.f16.f32 "
        "{%0,%1,%2,%3}, {%4,%5,%6,%7}, {%8,%9}, {%0,%1,%2,%3};"
        : "+f"(c[0]), "+f"(c[1]), "+f"(c[2]), "+f"(c[3])
        : "r"(a[0]), "r"(a[1]), "r"(a[2]), "r"(a[3]), "r"(b0), "r"(b1));
}

__global__ __launch_bounds__(128, 4)
void conv_mma(const float* __restrict__ bias, float* __restrict__ out) {
    __shared__ int s_i0[NCHUNK], s_i1[NCHUNK];
    __shared__ float s_bias[32];
    const int tid = threadIdx.x, wid = tid >> 5, lane = tid & 31;

    for (int c = tid; c < NCHUNK; c += 128) {
        int icb = c / 41, j = c - icb * 41;
        int k0 = 2 * j, k1 = (k0 < 80) ? k0 + 1 : 80;   // pad chunk reuses 80's addr (B half = 0)
        int kh0 = k0 / 9, kw0 = k0 - 9 * kh0;
        int kh1 = k1 / 9, kw1 = k1 - 9 * kh1;
        s_i0[c] = icb * 131072 + kh0 * 2048 + (kw0 & 1) * 1024 + (kw0 >> 1) * 32;
        s_i1[c] = icb * 131072 + kh1 * 2048 + (kw1 & 1) * 1024 + (kw1 >> 1) * 32;
    }
    if (tid < 32) s_bias[tid] = bias[tid];
    __syncthreads();

    // warp-tile: 1568 = 32 b x 49 m16 tiles; pos = tile*16 + row
    const int gidx = blockIdx.x * 4 + wid;
    const int b    = gidx / 49;
    const int tile = gidx - b * 49;
    const int pos_a = tile * 16 + (lane >> 2);
    const int pos_b = pos_a + 8;
    const int oh_a = pos_a / 28, ow_a = pos_a - 28 * oh_a;
    const int oh_b = pos_b / 28, ow_b = pos_b - 28 * oh_b;
    const uint32_t oA = (uint32_t)(oh_a * 4096 + ow_a * 32 + (lane & 3) * 8);
    const uint32_t oB = (uint32_t)(oh_b * 4096 + ow_b * 32 + (lane & 3) * 8);
    const unsigned char* xb  = g_x  + (size_t)b * (32u * 131072u);
    const unsigned char* wbp = g_wb + ((lane >> 2) * 32 + (lane & 3) * 8);

    float acc[4][4];
    #pragma unroll
    for (int g = 0; g < 4; ++g)
        #pragma unroll
        for (int q = 0; q < 4; ++q) acc[g][q] = 0.f;

    // depth-1 prefetch (proven best structure)
    uint2 A[4];                  // .x = hi, .y = lo
    uint2 Bv[4];                 // hi-limb b fragment per g
    {
        const int u0 = s_i0[0], u1 = s_i1[0];
        A[0] = *(const uint2*)(xb + u0 + oA);
        A[1] = *(const uint2*)(xb + u0 + oB);
        A[2] = *(const uint2*)(xb + u1 + oA);
        A[3] = *(const uint2*)(xb + u1 + oB);
        #pragma unroll
        for (int g = 0; g < 4; ++g) Bv[g] = *(const uint2*)(wbp + g * 256);
    }

    #pragma unroll 2
    for (int c = 0; c < NCHUNK; ++c) {
        uint2 nA[4];
        uint2 nB[4];
        const int cn = (c + 1 < NCHUNK) ? c + 1 : c;
        {
            const int u0 = s_i0[cn], u1 = s_i1[cn];
            nA[0] = *(const uint2*)(xb + u0 + oA);
            nA[1] = *(const uint2*)(xb + u0 + oB);
            nA[2] = *(const uint2*)(xb + u1 + oA);
            nA[3] = *(const uint2*)(xb + u1 + oB);
            const unsigned char* wp = wbp + (size_t)cn * 1024;
            #pragma unroll
            for (int g = 0; g < 4; ++g) nB[g] = *(const uint2*)(wp + g * 256);
        }
        uint32_t Ah[4] = {A[0].x, A[1].x, A[2].x, A[3].x};
        uint32_t Al[4] = {A[0].y, A[1].y, A[2].y, A[3].y};
        // product-major order: same-accumulator MMAs are 4 apart
        #pragma unroll
        for (int g = 0; g < 4; ++g) mma_f32(acc[g], Ah, Bv[g].x, Bv[g].y);   // xh * wh
        #pragma unroll
        for (int g = 0; g < 4; ++g) mma_f32(acc[g], Al, Bv[g].x, Bv[g].y);   // xl * wh
        #pragma unroll
        for (int k = 0; k < 4; ++k) { A[k] = nA[k]; Bv[k] = nB[k]; }
    }

    // epilogue: bias + squash + T=8 broadcast
    float4* o4 = reinterpret_cast<float4*>(out);
    const size_t ob = (size_t)b * NPOS;
    #pragma unroll
    for (int g = 0; g < 4; ++g) {
        #pragma unroll
        for (int q = 0; q < 4; ++q) {
            const int pos = (q < 2) ? pos_a : pos_b;
            const int oc  = g * 8 + (lane & 3) * 2 + (q & 1);
            float v = acc[g][q] + s_bias[oc];
            float sq = 8.f * v * v;
            float sv = v * (sq / (1.f + sq)) * rsqrtf(sq + 1e-8f);
            float4 f4 = make_float4(sv, sv, sv, sv);
            size_t idx = (ob + (size_t)(oc * 784 + pos)) * 2;
            o4[idx]     = f4;
            o4[idx + 1] = f4;
        }
    }
}

extern "C" void kernel_launch(void* const* d_in, const int* in_sizes, int n_in,
                              void* d_out, int out_size) {
    const float* x    = (const float*)d_in[0];
    const float* W    = (const float*)d_in[1];
    const float* bias = (const float*)d_in[2];
    float* out = (float*)d_out;

    xprep<<<2097152 / 256, 256>>>(x);
    wprep<<<(NCHUNK * 128 + 255) / 256, 256>>>(W);
    conv_mma<<<392, 128>>>(bias, out);   // 392 CTAs = 1568 warp-tiles / 4
}

// round 14
// speedup vs baseline: 1.4631x; 1.1291x over previous
#include <cuda_runtime.h>
#include <cuda_fp16.h>
#include <cstdint>

#define B_     32
#define NPOS   25088
#define NCHUNK 1312     // 32 icb * 41 k16-chunks (koff padded 81->82)

// staged x: [b][icb][ih64][parity2][q32][ic8 x 2B] fp16 -> 65536 B per (b,icb)
__device__ __align__(16) unsigned char g_x[32u * 32u * 65536u];
// packed B fragments (fp16): [chunk][g4][col8][p4][8B] -> 1024 B per chunk
__device__ __align__(16) unsigned char g_wb[(size_t)NCHUNK * 1024u];

// ---------------- x prep: f32 -> fp16, parity-split staged layout ----------------
__global__ void xprep(const float* __restrict__ x) {
    int i = blockIdx.x * 256 + threadIdx.x;          // 2097152 total
    int q = i & 31, r = (i >> 5) & 63, icb = (i >> 11) & 31, b = i >> 16;
    const float* xp = x + (((size_t)b * 256 + icb * 8) * 64 + r) * 64 + 2 * q;
    uint32_t h0[4], h1[4];                           // parity0 (iw=2q), parity1 (iw=2q+1)
    #pragma unroll
    for (int j = 0; j < 4; ++j) {                    // j = ic pair
        uint32_t ha = 0, hb = 0;
        #pragma unroll
        for (int e = 0; e < 2; ++e) {
            float2 v = *reinterpret_cast<const float2*>(xp + (size_t)(2 * j + e) * 4096);
            ha |= (uint32_t)__half_as_ushort(__float2half_rn(v.x)) << (e * 16);
            hb |= (uint32_t)__half_as_ushort(__float2half_rn(v.y)) << (e * 16);
        }
        h0[j] = ha; h1[j] = hb;
    }
    size_t ub = (size_t)(b * 32 + icb) * 65536u + (uint32_t)r * 1024u + (uint32_t)q * 16u;
    *reinterpret_cast<uint4*>(g_x + ub)       = make_uint4(h0[0], h0[1], h0[2], h0[3]);
    *reinterpret_cast<uint4*>(g_x + ub + 512) = make_uint4(h1[0], h1[1], h1[2], h1[3]);
}

// ---------------- W prep: B fragments fp16 (8B per lane) ----------------
__global__ void wprep(const float* __restrict__ W) {
    int i = blockIdx.x * 256 + threadIdx.x;          // NCHUNK*128 = 167936
    if (i >= NCHUNK * 128) return;
    int p = i & 3, oc = (i >> 2) & 31, c = i >> 7;
    int icb = c / 41, j = c - icb * 41;
    int k0 = 2 * j, k1 = k0 + 1;                     // k1 == 81 -> zero pad
    unsigned short hh[4];
    #pragma unroll
    for (int kk = 0; kk < 2; ++kk) {
        int koff = kk ? k1 : k0;
        #pragma unroll
        for (int e = 0; e < 2; ++e) {
            int ic = icb * 8 + 2 * p + e;
            float v = (koff <= 80) ? W[((size_t)oc * 256 + ic) * 81 + koff] : 0.f;
            hh[kk * 2 + e] = __half_as_ushort(__float2half_rn(v));
        }
    }
    uint2 pk = make_uint2((uint32_t)hh[0] | ((uint32_t)hh[1] << 16),
                          (uint32_t)hh[2] | ((uint32_t)hh[3] << 16));
    size_t off = (size_t)c * 1024 + (oc >> 3) * 256 + (oc & 7) * 32 + p * 8;
    *reinterpret_cast<uint2*>(g_wb + off) = pk;
}

// ---------------- main: single-product fp16 mma implicit GEMM ----------------
__device__ __forceinline__ void mma_f32(float* c, const uint32_t* a, uint32_t b0, uint32_t b1) {
    asm volatile("mma.sync.aligned.m16n8k16.row.col.f32.f16.f16.f32 "
        "{%0,%1,%2,%3}, {%4,%5,%6,%7}, {%8,%9}, {%0,%1,%2,%3};"
        : "+f"(c[0]), "+f"(c[1]), "+f"(c[2]), "+f"(c[3])
        : "r"(a[0]), "r"(a[1]), "r"(a[2]), "r"(a[3]), "r"(b0), "r"(b1));
}

__global__ __launch_bounds__(128, 4)
void conv_mma(const float* __restrict__ bias, float* __restrict__ out) {
    __shared__ int s_i0[NCHUNK], s_i1[NCHUNK];
    __shared__ float s_bias[32];
    const int tid = threadIdx.x, wid = tid >> 5, lane = tid & 31;

    for (int c = tid; c < NCHUNK; c += 128) {
        int icb = c / 41, j = c - icb * 41;
        int k0 = 2 * j, k1 = (k0 < 80) ? k0 + 1 : 80;   // pad chunk reuses 80's addr (B half = 0)
        int kh0 = k0 / 9, kw0 = k0 - 9 * kh0;
        int kh1 = k1 / 9, kw1 = k1 - 9 * kh1;
        s_i0[c] = icb * 65536 + kh0 * 1024 + (kw0 & 1) * 512 + (kw0 >> 1) * 16;
        s_i1[c] = icb * 65536 + kh1 * 1024 + (kw1 & 1) * 512 + (kw1 >> 1) * 16;
    }
    if (tid < 32) s_bias[tid] = bias[tid];
    __syncthreads();

    // warp-tile: 1568 = 32 b x 49 m16 tiles; pos = tile*16 + row
    const int gidx = blockIdx.x * 4 + wid;
    const int b    = gidx / 49;
    const int tile = gidx - b * 49;
    const int pos_a = tile * 16 + (lane >> 2);
    const int pos_b = pos_a + 8;
    const int oh_a = pos_a / 28, ow_a = pos_a - 28 * oh_a;
    const int oh_b = pos_b / 28, ow_b = pos_b - 28 * oh_b;
    // A addr = s_iX[c] + oh*2048 + ow*16 + (lane&3)*4
    const uint32_t oA = (uint32_t)(oh_a * 2048 + ow_a * 16 + (lane & 3) * 4);
    const uint32_t oB = (uint32_t)(oh_b * 2048 + ow_b * 16 + (lane & 3) * 4);
    const unsigned char* xb  = g_x  + (size_t)b * (32u * 65536u);
    const unsigned char* wbp = g_wb + ((lane >> 2) * 32 + (lane & 3) * 8);

    float acc[4][4];
    #pragma unroll
    for (int g = 0; g < 4; ++g)
        #pragma unroll
        for (int q = 0; q < 4; ++q) acc[g][q] = 0.f;

    // depth-1 prefetch (proven best structure)
    uint32_t A[4];
    uint2 Bv[4];
    {
        const int u0 = s_i0[0], u1 = s_i1[0];
        A[0] = *(const uint32_t*)(xb + u0 + oA);
        A[1] = *(const uint32_t*)(xb + u0 + oB);
        A[2] = *(const uint32_t*)(xb + u1 + oA);
        A[3] = *(const uint32_t*)(xb + u1 + oB);
        #pragma unroll
        for (int g = 0; g < 4; ++g) Bv[g] = *(const uint2*)(wbp + g * 256);
    }

    #pragma unroll 2
    for (int c = 0; c < NCHUNK; ++c) {
        uint32_t nA[4];
        uint2 nB[4];
        const int cn = (c + 1 < NCHUNK) ? c + 1 : c;
        {
            const int u0 = s_i0[cn], u1 = s_i1[cn];
            nA[0] = *(const uint32_t*)(xb + u0 + oA);
            nA[1] = *(const uint32_t*)(xb + u0 + oB);
            nA[2] = *(const uint32_t*)(xb + u1 + oA);
            nA[3] = *(const uint32_t*)(xb + u1 + oB);
            const unsigned char* wp = wbp + (size_t)cn * 1024;
            #pragma unroll
            for (int g = 0; g < 4; ++g) nB[g] = *(const uint2*)(wp + g * 256);
        }
        #pragma unroll
        for (int g = 0; g < 4; ++g) mma_f32(acc[g], A, Bv[g].x, Bv[g].y);
        #pragma unroll
        for (int k = 0; k < 4; ++k) { A[k] = nA[k]; Bv[k] = nB[k]; }
    }

    // epilogue: bias + squash + T=8 broadcast
    float4* o4 = reinterpret_cast<float4*>(out);
    const size_t ob = (size_t)b * NPOS;
    #pragma unroll
    for (int g = 0; g < 4; ++g) {
        #pragma unroll
        for (int q = 0; q < 4; ++q) {
            const int pos = (q < 2) ? pos_a : pos_b;
            const int oc  = g * 8 + (lane & 3) * 2 + (q & 1);
            float v = acc[g][q] + s_bias[oc];
            float sq = 8.f * v * v;
            float sv = v * (sq / (1.f + sq)) * rsqrtf(sq + 1e-8f);
            float4 f4 = make_float4(sv, sv, sv, sv);
            size_t idx = (ob + (size_t)(oc * 784 + pos)) * 2;
            o4[idx]     = f4;
            o4[idx + 1] = f4;
        }
    }
}

extern "C" void kernel_launch(void* const* d_in, const int* in_sizes, int n_in,
                              void* d_out, int out_size) {
    const float* x    = (const float*)d_in[0];
    const float* W    = (const float*)d_in[1];
    const float* bias = (const float*)d_in[2];
    float* out = (float*)d_out;

    xprep<<<2097152 / 256, 256>>>(x);
    wprep<<<(NCHUNK * 128 + 255) / 256, 256>>>(W);
    conv_mma<<<392, 128>>>(bias, out);   // 392 CTAs = 1568 warp-tiles / 4
}

// round 15
// speedup vs baseline: 1.6144x; 1.1034x over previous
#include <cuda_runtime.h>
#include <cuda_fp16.h>
#include <cstdint>

#define B_     32
#define NPOS   25088
#define NCHUNK 1312     // 32 icb * 41 k16-chunks (koff padded 81->82)

// staged x: [b][icb][ih64][parity2][q32][ic8 x 2B] fp16 -> 65536 B per (b,icb)
__device__ __align__(16) unsigned char g_x[32u * 32u * 65536u];
// packed B fragments (fp16): [chunk][g4][col8][p4][8B] -> 1024 B per chunk
__device__ __align__(16) unsigned char g_wb[(size_t)NCHUNK * 1024u];

// ---------------- x prep: f32 -> fp16, parity-split staged layout ----------------
__global__ void xprep(const float* __restrict__ x) {
    int i = blockIdx.x * 256 + threadIdx.x;          // 2097152 total
    int q = i & 31, r = (i >> 5) & 63, icb = (i >> 11) & 31, b = i >> 16;
    const float* xp = x + (((size_t)b * 256 + icb * 8) * 64 + r) * 64 + 2 * q;
    uint32_t h0[4], h1[4];                           // parity0 (iw=2q), parity1 (iw=2q+1)
    #pragma unroll
    for (int j = 0; j < 4; ++j) {                    // j = ic pair
        uint32_t ha = 0, hb = 0;
        #pragma unroll
        for (int e = 0; e < 2; ++e) {
            float2 v = *reinterpret_cast<const float2*>(xp + (size_t)(2 * j + e) * 4096);
            ha |= (uint32_t)__half_as_ushort(__float2half_rn(v.x)) << (e * 16);
            hb |= (uint32_t)__half_as_ushort(__float2half_rn(v.y)) << (e * 16);
        }
        h0[j] = ha; h1[j] = hb;
    }
    size_t ub = (size_t)(b * 32 + icb) * 65536u + (uint32_t)r * 1024u + (uint32_t)q * 16u;
    *reinterpret_cast<uint4*>(g_x + ub)       = make_uint4(h0[0], h0[1], h0[2], h0[3]);
    *reinterpret_cast<uint4*>(g_x + ub + 512) = make_uint4(h1[0], h1[1], h1[2], h1[3]);
}

// ---------------- W prep: B fragments fp16 (8B per lane) ----------------
__global__ void wprep(const float* __restrict__ W) {
    int i = blockIdx.x * 256 + threadIdx.x;          // NCHUNK*128 = 167936
    if (i >= NCHUNK * 128) return;
    int p = i & 3, oc = (i >> 2) & 31, c = i >> 7;
    int icb = c / 41, j = c - icb * 41;
    int k0 = 2 * j, k1 = k0 + 1;                     // k1 == 81 -> zero pad
    unsigned short hh[4];
    #pragma unroll
    for (int kk = 0; kk < 2; ++kk) {
        int koff = kk ? k1 : k0;
        #pragma unroll
        for (int e = 0; e < 2; ++e) {
            int ic = icb * 8 + 2 * p + e;
            float v = (koff <= 80) ? W[((size_t)oc * 256 + ic) * 81 + koff] : 0.f;
            hh[kk * 2 + e] = __half_as_ushort(__float2half_rn(v));
        }
    }
    uint2 pk = make_uint2((uint32_t)hh[0] | ((uint32_t)hh[1] << 16),
                          (uint32_t)hh[2] | ((uint32_t)hh[3] << 16));
    size_t off = (size_t)c * 1024 + (oc >> 3) * 256 + (oc & 7) * 32 + p * 8;
    *reinterpret_cast<uint2*>(g_wb + off) = pk;
}

// ---------------- main: fp16 mma, smem-shared B (cp.async 4-deep ring) ----------------
__device__ __forceinline__ void mma_f32(float* c, const uint32_t* a, uint32_t b0, uint32_t b1) {
    asm volatile("mma.sync.aligned.m16n8k16.row.col.f32.f16.f16.f32 "
        "{%0,%1,%2,%3}, {%4,%5,%6,%7}, {%8,%9}, {%0,%1,%2,%3};"
        : "+f"(c[0]), "+f"(c[1]), "+f"(c[2]), "+f"(c[3])
        : "r"(a[0]), "r"(a[1]), "r"(a[2]), "r"(a[3]), "r"(b0), "r"(b1));
}
__device__ __forceinline__ void cpa8(void* smem, const void* gmem) {
    uint32_t s = (uint32_t)__cvta_generic_to_shared(smem);
    asm volatile("cp.async.ca.shared.global [%0], [%1], 8;" :: "r"(s), "l"(gmem));
}
__device__ __forceinline__ void cpa_commit() { asm volatile("cp.async.commit_group;" ::); }
__device__ __forceinline__ void cpa_wait2()  { asm volatile("cp.async.wait_group 2;" ::); }

__global__ __launch_bounds__(128, 4)
void conv_mma(const float* __restrict__ bias, float* __restrict__ out) {
    __shared__ int s_i0[NCHUNK], s_i1[NCHUNK];
    __shared__ float s_bias[32];
    __shared__ __align__(16) unsigned char s_B[4][1024];   // B chunk ring
    const int tid = threadIdx.x, wid = tid >> 5, lane = tid & 31;

    for (int c = tid; c < NCHUNK; c += 128) {
        int icb = c / 41, j = c - icb * 41;
        int k0 = 2 * j, k1 = (k0 < 80) ? k0 + 1 : 80;   // pad chunk reuses 80's addr (B half = 0)
        int kh0 = k0 / 9, kw0 = k0 - 9 * kh0;
        int kh1 = k1 / 9, kw1 = k1 - 9 * kh1;
        s_i0[c] = icb * 65536 + kh0 * 1024 + (kw0 & 1) * 512 + (kw0 >> 1) * 16;
        s_i1[c] = icb * 65536 + kh1 * 1024 + (kw1 & 1) * 512 + (kw1 >> 1) * 16;
    }
    if (tid < 32) s_bias[tid] = bias[tid];
    __syncthreads();

    // warp-tile: 1568 = 32 b x 49 m16 tiles; pos = tile*16 + row
    const int gidx = blockIdx.x * 4 + wid;
    const int b    = gidx / 49;
    const int tile = gidx - b * 49;
    const int pos_a = tile * 16 + (lane >> 2);
    const int pos_b = pos_a + 8;
    const int oh_a = pos_a / 28, ow_a = pos_a - 28 * oh_a;
    const int oh_b = pos_b / 28, ow_b = pos_b - 28 * oh_b;
    const uint32_t oA = (uint32_t)(oh_a * 2048 + ow_a * 16 + (lane & 3) * 4);
    const uint32_t oB = (uint32_t)(oh_b * 2048 + ow_b * 16 + (lane & 3) * 4);
    const unsigned char* xb = g_x + (size_t)b * (32u * 65536u);
    const uint32_t bfo = (uint32_t)((lane >> 2) * 32 + (lane & 3) * 8);   // B frag offset per g

    float acc[4][4];
    #pragma unroll
    for (int g = 0; g < 4; ++g)
        #pragma unroll
        for (int q = 0; q < 4; ++q) acc[g][q] = 0.f;

    // prologue: B chunks 0..2 into ring, one group each; A chunk 0 in regs
    #pragma unroll
    for (int s = 0; s < 3; ++s) {
        cpa8(&s_B[s][tid * 8], g_wb + (size_t)s * 1024 + tid * 8);
        cpa_commit();
    }
    uint32_t A[4];
    {
        const int u0 = s_i0[0], u1 = s_i1[0];
        A[0] = *(const uint32_t*)(xb + u0 + oA);
        A[1] = *(const uint32_t*)(xb + u0 + oB);
        A[2] = *(const uint32_t*)(xb + u1 + oA);
        A[3] = *(const uint32_t*)(xb + u1 + oB);
    }

    #pragma unroll 2
    for (int c = 0; c < NCHUNK; ++c) {
        cpa_wait2();          // B[c] (and B[c+1]) arrived for this warp
        __syncthreads();      // visible to all; all warps done reading B[c-1]
        const int cn3 = c + 3;
        if (cn3 < NCHUNK)     // refill slot (c+3)&3 = (c-1)&3 — readers all past it
            cpa8(&s_B[cn3 & 3][tid * 8], g_wb + (size_t)cn3 * 1024 + tid * 8);
        cpa_commit();         // commit every iter (keeps group accounting uniform)

        // B fragments from smem (4x LDS.64, conflict-free)
        const unsigned char* sp = s_B[c & 3] + bfo;
        uint2 Bv[4];
        #pragma unroll
        for (int g = 0; g < 4; ++g) Bv[g] = *(const uint2*)(sp + g * 256);

        // prefetch next A
        uint32_t nA[4];
        const int cn = (c + 1 < NCHUNK) ? c + 1 : c;
        {
            const int u0 = s_i0[cn], u1 = s_i1[cn];
            nA[0] = *(const uint32_t*)(xb + u0 + oA);
            nA[1] = *(const uint32_t*)(xb + u0 + oB);
            nA[2] = *(const uint32_t*)(xb + u1 + oA);
            nA[3] = *(const uint32_t*)(xb + u1 + oB);
        }
        #pragma unroll
        for (int g = 0; g < 4; ++g) mma_f32(acc[g], A, Bv[g].x, Bv[g].y);
        #pragma unroll
        for (int k = 0; k < 4; ++k) A[k] = nA[k];
    }

    // epilogue: bias + squash + T=8 broadcast
    float4* o4 = reinterpret_cast<float4*>(out);
    const size_t ob = (size_t)b * NPOS;
    #pragma unroll
    for (int g = 0; g < 4; ++g) {
        #pragma unroll
        for (int q = 0; q < 4; ++q) {
            const int pos = (q < 2) ? pos_a : pos_b;
            const int oc  = g * 8 + (lane & 3) * 2 + (q & 1);
            float v = acc[g][q] + s_bias[oc];
            float sq = 8.f * v * v;
            float sv = v * (sq / (1.f + sq)) * rsqrtf(sq + 1e-8f);
            float4 f4 = make_float4(sv, sv, sv, sv);
            size_t idx = (ob + (size_t)(oc * 784 + pos)) * 2;
            o4[idx]     = f4;
            o4[idx + 1] = f4;
        }
    }
}

extern "C" void kernel_launch(void* const* d_in, const int* in_sizes, int n_in,
                              void* d_out, int out_size) {
    const float* x    = (const float*)d_in[0];
    const float* W    = (const float*)d_in[1];
    const float* bias = (const float*)d_in[2];
    float* out = (float*)d_out;

    xprep<<<2097152 / 256, 256>>>(x);
    wprep<<<(NCHUNK * 128 + 255) / 256, 256>>>(W);
    conv_mma<<<392, 128>>>(bias, out);   // 392 CTAs = 1568 warp-tiles / 4
}

// round 16
// speedup vs baseline: 2.0363x; 1.2613x over previous
#include <cuda_runtime.h>
#include <cuda_fp16.h>
#include <cstdint>

#define B_     32
#define NPOS   25088
#define NCHUNK 1312     // 32 icb * 41 k16-chunks (koff padded 81->82)
#define NITER  (NCHUNK/2)

// staged x: [b][icb][ih64][parity2][q32][ic8 x 2B] fp16 -> 65536 B per (b,icb)
__device__ __align__(16) unsigned char g_x[32u * 32u * 65536u];
// packed B fragments (fp16): [chunk][g4][col8][p4][8B] -> 1024 B per chunk
__device__ __align__(16) unsigned char g_wb[(size_t)NCHUNK * 1024u];

// ---------------- x prep: f32 -> fp16, parity-split staged layout ----------------
__global__ void xprep(const float* __restrict__ x) {
    int i = blockIdx.x * 256 + threadIdx.x;          // 2097152 total
    int q = i & 31, r = (i >> 5) & 63, icb = (i >> 11) & 31, b = i >> 16;
    const float* xp = x + (((size_t)b * 256 + icb * 8) * 64 + r) * 64 + 2 * q;
    uint32_t h0[4], h1[4];                           // parity0 (iw=2q), parity1 (iw=2q+1)
    #pragma unroll
    for (int j = 0; j < 4; ++j) {                    // j = ic pair
        uint32_t ha = 0, hb = 0;
        #pragma unroll
        for (int e = 0; e < 2; ++e) {
            float2 v = *reinterpret_cast<const float2*>(xp + (size_t)(2 * j + e) * 4096);
            ha |= (uint32_t)__half_as_ushort(__float2half_rn(v.x)) << (e * 16);
            hb |= (uint32_t)__half_as_ushort(__float2half_rn(v.y)) << (e * 16);
        }
        h0[j] = ha; h1[j] = hb;
    }
    size_t ub = (size_t)(b * 32 + icb) * 65536u + (uint32_t)r * 1024u + (uint32_t)q * 16u;
    *reinterpret_cast<uint4*>(g_x + ub)       = make_uint4(h0[0], h0[1], h0[2], h0[3]);
    *reinterpret_cast<uint4*>(g_x + ub + 512) = make_uint4(h1[0], h1[1], h1[2], h1[3]);
}

// ---------------- W prep: B fragments fp16 (8B per lane) ----------------
__global__ void wprep(const float* __restrict__ W) {
    int i = blockIdx.x * 256 + threadIdx.x;          // NCHUNK*128 = 167936
    if (i >= NCHUNK * 128) return;
    int p = i & 3, oc = (i >> 2) & 31, c = i >> 7;
    int icb = c / 41, j = c - icb * 41;
    int k0 = 2 * j, k1 = k0 + 1;                     // k1 == 81 -> zero pad
    unsigned short hh[4];
    #pragma unroll
    for (int kk = 0; kk < 2; ++kk) {
        int koff = kk ? k1 : k0;
        #pragma unroll
        for (int e = 0; e < 2; ++e) {
            int ic = icb * 8 + 2 * p + e;
            float v = (koff <= 80) ? W[((size_t)oc * 256 + ic) * 81 + koff] : 0.f;
            hh[kk * 2 + e] = __half_as_ushort(__float2half_rn(v));
        }
    }
    uint2 pk = make_uint2((uint32_t)hh[0] | ((uint32_t)hh[1] << 16),
                          (uint32_t)hh[2] | ((uint32_t)hh[3] << 16));
    size_t off = (size_t)c * 1024 + (oc >> 3) * 256 + (oc & 7) * 32 + p * 8;
    *reinterpret_cast<uint2*>(g_wb + off) = pk;
}

// ---------------- main: fp16 mma, smem B ring, 2 chunks per sync step ----------------
__device__ __forceinline__ void mma_f32(float* c, const uint32_t* a, uint32_t b0, uint32_t b1) {
    asm volatile("mma.sync.aligned.m16n8k16.row.col.f32.f16.f16.f32 "
        "{%0,%1,%2,%3}, {%4,%5,%6,%7}, {%8,%9}, {%0,%1,%2,%3};"
        : "+f"(c[0]), "+f"(c[1]), "+f"(c[2]), "+f"(c[3])
        : "r"(a[0]), "r"(a[1]), "r"(a[2]), "r"(a[3]), "r"(b0), "r"(b1));
}
__device__ __forceinline__ void cpa16s(void* smem, const void* gmem) {
    uint32_t s = (uint32_t)__cvta_generic_to_shared(smem);
    asm volatile("cp.async.ca.shared.global [%0], [%1], 16;" :: "r"(s), "l"(gmem));
}
__device__ __forceinline__ void cpa_commit() { asm volatile("cp.async.commit_group;" ::); }
__device__ __forceinline__ void cpa_wait2()  { asm volatile("cp.async.wait_group 2;" ::); }

__global__ __launch_bounds__(128, 4)
void conv_mma(const float* __restrict__ bias, float* __restrict__ out) {
    __shared__ int s_i0[NCHUNK], s_i1[NCHUNK];
    __shared__ float s_bias[32];
    __shared__ __align__(16) unsigned char s_B[4][2048];   // ring: 4 slots x 2 chunks
    const int tid = threadIdx.x, wid = tid >> 5, lane = tid & 31;

    for (int c = tid; c < NCHUNK; c += 128) {
        int icb = c / 41, j = c - icb * 41;
        int k0 = 2 * j, k1 = (k0 < 80) ? k0 + 1 : 80;   // pad chunk reuses 80's addr (B half = 0)
        int kh0 = k0 / 9, kw0 = k0 - 9 * kh0;
        int kh1 = k1 / 9, kw1 = k1 - 9 * kh1;
        s_i0[c] = icb * 65536 + kh0 * 1024 + (kw0 & 1) * 512 + (kw0 >> 1) * 16;
        s_i1[c] = icb * 65536 + kh1 * 1024 + (kw1 & 1) * 512 + (kw1 >> 1) * 16;
    }
    if (tid < 32) s_bias[tid] = bias[tid];
    __syncthreads();

    // warp-tile: 1568 = 32 b x 49 m16 tiles; pos = tile*16 + row
    const int gidx = blockIdx.x * 4 + wid;
    const int b    = gidx / 49;
    const int tile = gidx - b * 49;
    const int pos_a = tile * 16 + (lane >> 2);
    const int pos_b = pos_a + 8;
    const int oh_a = pos_a / 28, ow_a = pos_a - 28 * oh_a;
    const int oh_b = pos_b / 28, ow_b = pos_b - 28 * oh_b;
    const uint32_t oA = (uint32_t)(oh_a * 2048 + ow_a * 16 + (lane & 3) * 4);
    const uint32_t oB = (uint32_t)(oh_b * 2048 + ow_b * 16 + (lane & 3) * 4);
    const unsigned char* xb = g_x + (size_t)b * (32u * 65536u);
    const uint32_t bfo = (uint32_t)((lane >> 2) * 32 + (lane & 3) * 8);   // B frag offset per g

    float acc[4][4];
    #pragma unroll
    for (int g = 0; g < 4; ++g)
        #pragma unroll
        for (int q = 0; q < 4; ++q) acc[g][q] = 0.f;

    // prologue: slots 0..2 <- chunk pairs 0..2 (one group each); A regs for pair 0
    #pragma unroll
    for (int s = 0; s < 3; ++s) {
        cpa16s(&s_B[s][tid * 16], g_wb + (size_t)s * 2048 + tid * 16);
        cpa_commit();
    }
    uint32_t A[2][4];
    #pragma unroll
    for (int cc = 0; cc < 2; ++cc) {
        const int u0 = s_i0[cc], u1 = s_i1[cc];
        A[cc][0] = *(const uint32_t*)(xb + u0 + oA);
        A[cc][1] = *(const uint32_t*)(xb + u0 + oB);
        A[cc][2] = *(const uint32_t*)(xb + u1 + oA);
        A[cc][3] = *(const uint32_t*)(xb + u1 + oB);
    }

    for (int it = 0; it < NITER; ++it) {
        cpa_wait2();          // slot it&3 arrived for this warp
        __syncthreads();      // visible to all; all warps done reading slot (it-1)&3
        const int sn = it + 3;
        if (sn < NITER)       // refill slot (it+3)&3 = (it-1)&3
            cpa16s(&s_B[sn & 3][tid * 16], g_wb + (size_t)sn * 2048 + tid * 16);
        cpa_commit();

        const unsigned char* sp = s_B[it & 3] + bfo;
        // prefetch A for next pair
        uint32_t nA[2][4];
        const int base = 2 * it + 2;
        #pragma unroll
        for (int cc = 0; cc < 2; ++cc) {
            const int cn = (base + cc < NCHUNK) ? base + cc : NCHUNK - 1;
            const int u0 = s_i0[cn], u1 = s_i1[cn];
            nA[cc][0] = *(const uint32_t*)(xb + u0 + oA);
            nA[cc][1] = *(const uint32_t*)(xb + u0 + oB);
            nA[cc][2] = *(const uint32_t*)(xb + u1 + oA);
            nA[cc][3] = *(const uint32_t*)(xb + u1 + oB);
        }
        // compute both chunks of this slot
        #pragma unroll
        for (int cc = 0; cc < 2; ++cc) {
            uint2 Bv[4];
            #pragma unroll
            for (int g = 0; g < 4; ++g) Bv[g] = *(const uint2*)(sp + cc * 1024 + g * 256);
            #pragma unroll
            for (int g = 0; g < 4; ++g) mma_f32(acc[g], A[cc], Bv[g].x, Bv[g].y);
        }
        #pragma unroll
        for (int cc = 0; cc < 2; ++cc)
            #pragma unroll
            for (int k = 0; k < 4; ++k) A[cc][k] = nA[cc][k];
    }

    // epilogue: bias + squash + T=8 broadcast
    float4* o4 = reinterpret_cast<float4*>(out);
    const size_t ob = (size_t)b * NPOS;
    #pragma unroll
    for (int g = 0; g < 4; ++g) {
        #pragma unroll
        for (int q = 0; q < 4; ++q) {
            const int pos = (q < 2) ? pos_a : pos_b;
            const int oc  = g * 8 + (lane & 3) * 2 + (q & 1);
            float v = acc[g][q] + s_bias[oc];
            float sq = 8.f * v * v;
            float sv = v * (sq / (1.f + sq)) * rsqrtf(sq + 1e-8f);
            float4 f4 = make_float4(sv, sv, sv, sv);
            size_t idx = (ob + (size_t)(oc * 784 + pos)) * 2;
            o4[idx]     = f4;
            o4[idx + 1] = f4;
        }
    }
}

extern "C" void kernel_launch(void* const* d_in, const int* in_sizes, int n_in,
                              void* d_out, int out_size) {
    const float* x    = (const float*)d_in[0];
    const float* W    = (const float*)d_in[1];
    const float* bias = (const float*)d_in[2];
    float* out = (float*)d_out;

    xprep<<<2097152 / 256, 256>>>(x);
    wprep<<<(NCHUNK * 128 + 255) / 256, 256>>>(W);
    conv_mma<<<392, 128>>>(bias, out);   // 392 CTAs = 1568 warp-tiles / 4
}